// round 1
// baseline (speedup 1.0000x reference)
#include <cuda_runtime.h>

// Problem constants
#define HW      16384      // 128*128
#define CIN     512
#define CH      30
#define NPAIR   15         // 30 channels as 15 f32x2 pairs
#define NCLS    17
#define NBATCH  8
#define BN_EPS  1e-5f
#define TPB     256

typedef unsigned long long u64;

// ---- packed f32x2 helpers (Blackwell sm_100a: fma.rn.f32x2) ----
__device__ __forceinline__ u64 fma2(u64 a, u64 b, u64 c) {
    u64 d;
    asm("fma.rn.f32x2 %0, %1, %2, %3;" : "=l"(d) : "l"(a), "l"(b), "l"(c));
    return d;
}
__device__ __forceinline__ u64 dup2(float v) {
    u64 d;
    asm("mov.b64 %0, {%1, %1};" : "=l"(d) : "f"(v));
    return d;
}
__device__ __forceinline__ u64 pack2(float lo, float hi) {
    u64 d;
    asm("mov.b64 %0, {%1, %2};" : "=l"(d) : "f"(lo), "f"(hi));
    return d;
}
__device__ __forceinline__ float2 unpack2(u64 v) {
    float lo, hi;
    asm("mov.b64 {%0, %1}, %2;" : "=f"(lo), "=f"(hi) : "l"(v));
    return make_float2(lo, hi);
}

// smem layout (dynamic):
//   [0, 61440)            u64 wpack[512*15]   : (w0'[2p][c], w0'[2p+1][c]) BN-folded
//   [61440, 63480)        float w1s[510]
//   [63480, 63548)        float b1s[17]
//   [63548, 63668)        float b0f[30]       : BN-folded bias
#define SMEM_BYTES 63680

__global__ __launch_bounds__(TPB, 2) void fused_segnet_kernel(
    const float* __restrict__ x,
    const float* __restrict__ w0,
    const float* __restrict__ b0,
    const float* __restrict__ gamma,
    const float* __restrict__ beta,
    const float* __restrict__ mean,
    const float* __restrict__ var,
    const float* __restrict__ w1,
    const float* __restrict__ b1,
    float* __restrict__ dout,
    int write_logits)
{
    extern __shared__ unsigned char smem_raw[];
    u64*   wpack = (u64*)smem_raw;
    float* w1s   = (float*)(smem_raw + 61440);
    float* b1s   = w1s + 510;
    float* b0f   = b1s + NCLS;
    __shared__ float scale_s[CH];

    const int tid = threadIdx.x;

    // ---------- prologue: fold BN into conv0 weights/bias, stage small tensors ----------
    if (tid < CH) {
        float s = gamma[tid] * rsqrtf(var[tid] + BN_EPS);
        scale_s[tid] = s;
        b0f[tid] = (b0[tid] - mean[tid]) * s + beta[tid];
    }
    for (int i = tid; i < NCLS * CH; i += TPB) w1s[i] = w1[i];
    if (tid < NCLS) b1s[tid] = b1[tid];
    __syncthreads();

    for (int i = tid; i < CIN * NPAIR; i += TPB) {
        int c  = i / NPAIR;
        int po = i - c * NPAIR;
        int o0 = 2 * po, o1 = o0 + 1;
        wpack[i] = pack2(w0[o0 * CIN + c] * scale_s[o0],
                         w0[o1 * CIN + c] * scale_s[o1]);
    }
    __syncthreads();

    // ---------- mainloop: conv0 (512 -> 30) over a pixel pair per thread ----------
    const int pp = blockIdx.x * TPB + tid;     // pixel-pair index, 0..65535
    const int gp = pp << 1;                    // even global pixel index
    const int b  = gp >> 14;                   // gp / HW
    const int hw = gp & (HW - 1);

    const float* xb = x + ((size_t)b * CIN) * HW + hw;

    u64 acc0[NPAIR], acc1[NPAIR];
#pragma unroll
    for (int po = 0; po < NPAIR; po++) {
        u64 bi = pack2(b0f[2 * po], b0f[2 * po + 1]);
        acc0[po] = bi;
        acc1[po] = bi;
    }

#pragma unroll 4
    for (int c = 0; c < CIN; c++) {
        float2 xv = __ldcs((const float2*)(xb + (size_t)c * HW));
        u64 d0 = dup2(xv.x);
        u64 d1 = dup2(xv.y);
        const u64* wr = wpack + c * NPAIR;
#pragma unroll
        for (int po = 0; po < NPAIR; po++) {
            u64 w = wr[po];
            acc0[po] = fma2(w, d0, acc0[po]);
            acc1[po] = fma2(w, d1, acc1[po]);
        }
    }

    // ---------- epilogue: ReLU, conv1 (30 -> 17), argmax ----------
    float h0[CH], h1[CH];
#pragma unroll
    for (int po = 0; po < NPAIR; po++) {
        float2 a = unpack2(acc0[po]);
        h0[2 * po]     = fmaxf(a.x, 0.0f);
        h0[2 * po + 1] = fmaxf(a.y, 0.0f);
        float2 bb = unpack2(acc1[po]);
        h1[2 * po]     = fmaxf(bb.x, 0.0f);
        h1[2 * po + 1] = fmaxf(bb.y, 0.0f);
    }

    float lo0[NCLS], lo1[NCLS];
    float best0 = -__builtin_huge_valf(), best1 = -__builtin_huge_valf();
    int cls0 = 0, cls1 = 0;
#pragma unroll
    for (int k = 0; k < NCLS; k++) {
        float s0 = b1s[k], s1 = b1s[k];
#pragma unroll
        for (int j = 0; j < CH; j++) {
            float w = w1s[k * CH + j];
            s0 = fmaf(w, h0[j], s0);
            s1 = fmaf(w, h1[j], s1);
        }
        lo0[k] = s0;
        lo1[k] = s1;
        if (s0 > best0) { best0 = s0; cls0 = k; }   // strict > == first-max (jnp.argmax)
        if (s1 > best1) { best1 = s1; cls1 = k; }
    }

    // ---------- writes: res[b, k*30+j, hw] = (k==cls) * h[j] ----------
    float* res = dout + ((size_t)b * (NCLS * CH)) * HW + hw;
#pragma unroll
    for (int k = 0; k < NCLS; k++) {
        const bool m0 = (k == cls0);
        const bool m1 = (k == cls1);
#pragma unroll
        for (int j = 0; j < CH; j++) {
            float2 v = make_float2(m0 ? h0[j] : 0.0f, m1 ? h1[j] : 0.0f);
            __stcs((float2*)(res + (size_t)(k * CH + j) * HW), v);
        }
    }

    if (write_logits) {
        float* lg = dout + (size_t)NBATCH * (NCLS * CH) * HW
                         + ((size_t)b * NCLS) * HW + hw;
#pragma unroll
        for (int k = 0; k < NCLS; k++) {
            __stcs((float2*)(lg + (size_t)k * HW), make_float2(lo0[k], lo1[k]));
        }
    }
}

extern "C" void kernel_launch(void* const* d_in, const int* in_sizes, int n_in,
                              void* d_out, int out_size)
{
    const float* x     = (const float*)d_in[0];
    const float* w0    = (const float*)d_in[1];
    const float* b0    = (const float*)d_in[2];
    const float* gamma = (const float*)d_in[3];
    const float* beta  = (const float*)d_in[4];
    const float* mean  = (const float*)d_in[5];
    const float* var   = (const float*)d_in[6];
    const float* w1    = (const float*)d_in[7];
    const float* b1    = (const float*)d_in[8];

    // d_out layout assumed: res (8*510*128*128) followed by logits (8*17*128*128)
    const long long res_elems   = (long long)NBATCH * NCLS * CH * HW;  // 66,846,720
    const long long total_elems = res_elems + (long long)NBATCH * NCLS * HW;
    const int write_logits = ((long long)out_size >= total_elems) ? 1 : 0;

    static int smem_configured = 0;
    if (!smem_configured) {
        cudaFuncSetAttribute(fused_segnet_kernel,
                             cudaFuncAttributeMaxDynamicSharedMemorySize, SMEM_BYTES);
        smem_configured = 1;
    }

    const int n_pairs = NBATCH * HW / 2;        // 65536
    const int blocks  = n_pairs / TPB;          // 256
    fused_segnet_kernel<<<blocks, TPB, SMEM_BYTES>>>(
        x, w0, b0, gamma, beta, mean, var, w1, b1, (float*)d_out, write_logits);
}

// round 2
// speedup vs baseline: 1.1991x; 1.1991x over previous
#include <cuda_runtime.h>

// Problem constants
#define HW      16384      // 128*128
#define CIN     512
#define CH      30
#define NPAIR   15         // 30 channels as 15 f32x2 pairs
#define WROW    16         // padded weight row (u64s) -> 128B rows, 16B aligned v2 loads
#define NCLS    17
#define NBATCH  8
#define BN_EPS  1e-5f
#define TPB     256
#define PF      8          // prefetch depth (x channels in flight per thread)

typedef unsigned long long u64;

// ---- packed f32x2 helpers (Blackwell sm_100a: fma.rn.f32x2) ----
__device__ __forceinline__ u64 fma2(u64 a, u64 b, u64 c) {
    u64 d;
    asm("fma.rn.f32x2 %0, %1, %2, %3;" : "=l"(d) : "l"(a), "l"(b), "l"(c));
    return d;
}
__device__ __forceinline__ u64 dup2(float v) {
    u64 d;
    asm("mov.b64 %0, {%1, %1};" : "=l"(d) : "f"(v));
    return d;
}
__device__ __forceinline__ u64 pack2(float lo, float hi) {
    u64 d;
    asm("mov.b64 %0, {%1, %2};" : "=l"(d) : "f"(lo), "f"(hi));
    return d;
}
__device__ __forceinline__ float2 unpack2(u64 v) {
    float lo, hi;
    asm("mov.b64 {%0, %1}, %2;" : "=f"(lo), "=f"(hi) : "l"(v));
    return make_float2(lo, hi);
}

// smem layout (dynamic):
//   [0, 65536)        u64 wpack[512*16]  : BN-folded (w0'[2p][c], w0'[2p+1][c]), 128B rows
//   [65536, 67576)    float w1s[510]
//   [67576, 67644)    float b1s[17]
//   [67644, 67764)    float b0f[30]
#define SMEM_BYTES 67840

__global__ __launch_bounds__(TPB, 2) void fused_segnet_kernel(
    const float* __restrict__ x,
    const float* __restrict__ w0,
    const float* __restrict__ b0,
    const float* __restrict__ gamma,
    const float* __restrict__ beta,
    const float* __restrict__ mean,
    const float* __restrict__ var,
    const float* __restrict__ w1,
    const float* __restrict__ b1,
    float* __restrict__ dout,
    int write_logits)
{
    extern __shared__ unsigned char smem_raw[];
    u64*   wpack = (u64*)smem_raw;
    float* w1s   = (float*)(smem_raw + 65536);
    float* b1s   = w1s + 510;
    float* b0f   = b1s + NCLS;
    __shared__ float scale_s[CH];

    const int tid = threadIdx.x;

    // ---------- prologue: fold BN into conv0 weights/bias, stage small tensors ----------
    if (tid < CH) {
        float s = gamma[tid] * rsqrtf(var[tid] + BN_EPS);
        scale_s[tid] = s;
        b0f[tid] = (b0[tid] - mean[tid]) * s + beta[tid];
    }
    for (int i = tid; i < NCLS * CH; i += TPB) w1s[i] = w1[i];
    if (tid < NCLS) b1s[tid] = b1[tid];
    __syncthreads();

    for (int i = tid; i < CIN * NPAIR; i += TPB) {
        int c  = i / NPAIR;
        int po = i - c * NPAIR;
        int o0 = 2 * po, o1 = o0 + 1;
        wpack[(c << 4) + po] = pack2(w0[o0 * CIN + c] * scale_s[o0],
                                     w0[o1 * CIN + c] * scale_s[o1]);
    }
    __syncthreads();

    // ---------- mainloop: conv0 (512 -> 30) over a pixel pair per thread ----------
    const int pp = blockIdx.x * TPB + tid;     // pixel-pair index
    const int gp = pp << 1;                    // even global pixel index
    const int b  = gp >> 14;                   // gp / HW
    const int hw = gp & (HW - 1);

    const float* xb = x + ((size_t)b * CIN) * HW + hw;

    u64 acc0[NPAIR], acc1[NPAIR];
#pragma unroll
    for (int po = 0; po < NPAIR; po++) {
        u64 bi = pack2(b0f[2 * po], b0f[2 * po + 1]);
        acc0[po] = bi;
        acc1[po] = bi;
    }

    // register-resident x pipeline, PF channels deep
    float2 xbuf[PF];
#pragma unroll
    for (int i = 0; i < PF; i++)
        xbuf[i] = __ldcs((const float2*)(xb + (size_t)i * HW));

    for (int c0 = 0; c0 < CIN - PF; c0 += PF) {
#pragma unroll
        for (int i = 0; i < PF; i++) {
            const int c = c0 + i;
            float2 xv = xbuf[i];
            xbuf[i] = __ldcs((const float2*)(xb + (size_t)(c + PF) * HW));
            u64 d0 = dup2(xv.x);
            u64 d1 = dup2(xv.y);
            const ulonglong2* wv = (const ulonglong2*)(wpack + (c << 4));
#pragma unroll
            for (int q = 0; q < 7; q++) {
                ulonglong2 w = wv[q];
                acc0[2*q]   = fma2(w.x, d0, acc0[2*q]);
                acc1[2*q]   = fma2(w.x, d1, acc1[2*q]);
                acc0[2*q+1] = fma2(w.y, d0, acc0[2*q+1]);
                acc1[2*q+1] = fma2(w.y, d1, acc1[2*q+1]);
            }
            u64 w14 = wpack[(c << 4) + 14];
            acc0[14] = fma2(w14, d0, acc0[14]);
            acc1[14] = fma2(w14, d1, acc1[14]);
        }
    }
    // final PF channels (no prefetch)
    {
        const int c0 = CIN - PF;
#pragma unroll
        for (int i = 0; i < PF; i++) {
            const int c = c0 + i;
            float2 xv = xbuf[i];
            u64 d0 = dup2(xv.x);
            u64 d1 = dup2(xv.y);
            const ulonglong2* wv = (const ulonglong2*)(wpack + (c << 4));
#pragma unroll
            for (int q = 0; q < 7; q++) {
                ulonglong2 w = wv[q];
                acc0[2*q]   = fma2(w.x, d0, acc0[2*q]);
                acc1[2*q]   = fma2(w.x, d1, acc1[2*q]);
                acc0[2*q+1] = fma2(w.y, d0, acc0[2*q+1]);
                acc1[2*q+1] = fma2(w.y, d1, acc1[2*q+1]);
            }
            u64 w14 = wpack[(c << 4) + 14];
            acc0[14] = fma2(w14, d0, acc0[14]);
            acc1[14] = fma2(w14, d1, acc1[14]);
        }
    }

    // ---------- epilogue: ReLU, conv1 (30 -> 17), argmax, stream logits ----------
    float h0[CH], h1[CH];
#pragma unroll
    for (int po = 0; po < NPAIR; po++) {
        float2 a = unpack2(acc0[po]);
        h0[2 * po]     = fmaxf(a.x, 0.0f);
        h0[2 * po + 1] = fmaxf(a.y, 0.0f);
        float2 bb = unpack2(acc1[po]);
        h1[2 * po]     = fmaxf(bb.x, 0.0f);
        h1[2 * po + 1] = fmaxf(bb.y, 0.0f);
    }

    float* lg = dout + (size_t)NBATCH * (NCLS * CH) * HW
                     + ((size_t)b * NCLS) * HW + hw;

    float best0 = -__builtin_huge_valf(), best1 = -__builtin_huge_valf();
    int cls0 = 0, cls1 = 0;
#pragma unroll
    for (int k = 0; k < NCLS; k++) {
        float s0 = b1s[k], s1 = b1s[k];
#pragma unroll
        for (int j = 0; j < CH; j++) {
            float w = w1s[k * CH + j];
            s0 = fmaf(w, h0[j], s0);
            s1 = fmaf(w, h1[j], s1);
        }
        if (s0 > best0) { best0 = s0; cls0 = k; }   // strict > == first-max (jnp.argmax)
        if (s1 > best1) { best1 = s1; cls1 = k; }
        if (write_logits)
            __stcs((float2*)(lg + (size_t)k * HW), make_float2(s0, s1));
    }

    // ---------- writes: res[b, k*30+j, hw] = (k==cls) * h[j] ----------
    float* res = dout + ((size_t)b * (NCLS * CH)) * HW + hw;
#pragma unroll
    for (int k = 0; k < NCLS; k++) {
        const bool m0 = (k == cls0);
        const bool m1 = (k == cls1);
#pragma unroll
        for (int j = 0; j < CH; j++) {
            float2 v = make_float2(m0 ? h0[j] : 0.0f, m1 ? h1[j] : 0.0f);
            __stcs((float2*)(res + (size_t)(k * CH + j) * HW), v);
        }
    }
}

extern "C" void kernel_launch(void* const* d_in, const int* in_sizes, int n_in,
                              void* d_out, int out_size)
{
    const float* x     = (const float*)d_in[0];
    const float* w0    = (const float*)d_in[1];
    const float* b0    = (const float*)d_in[2];
    const float* gamma = (const float*)d_in[3];
    const float* beta  = (const float*)d_in[4];
    const float* mean  = (const float*)d_in[5];
    const float* var   = (const float*)d_in[6];
    const float* w1    = (const float*)d_in[7];
    const float* b1    = (const float*)d_in[8];

    // d_out layout: res (8*510*128*128) followed by logits (8*17*128*128)
    const long long res_elems   = (long long)NBATCH * NCLS * CH * HW;
    const long long total_elems = res_elems + (long long)NBATCH * NCLS * HW;
    const int write_logits = ((long long)out_size >= total_elems) ? 1 : 0;

    static int smem_configured = 0;
    if (!smem_configured) {
        cudaFuncSetAttribute(fused_segnet_kernel,
                             cudaFuncAttributeMaxDynamicSharedMemorySize, SMEM_BYTES);
        smem_configured = 1;
    }

    const int n_pairs = NBATCH * HW / 2;        // 65536
    const int blocks  = n_pairs / TPB;          // 256
    fused_segnet_kernel<<<blocks, TPB, SMEM_BYTES>>>(
        x, w0, b0, gamma, beta, mean, var, w1, b1, (float*)d_out, write_logits);
}